// round 16
// baseline (speedup 1.0000x reference)
#include <cuda_runtime.h>
#include <cstdint>

typedef unsigned long long u64;
typedef unsigned int u32;

// ---------------------------------------------------------------------------
// GhInfer_19104014533112 : YOLO NMS post-process on GB300 — 3-launch pipeline
// out[0:6000) det (1000x6) fp32 ; out[6000:1234800) x (1,3,640,640) fp32
// in[0] img int32 (640*640*3) ; in[1] pred fp32 (8*25200*85), batch 0 only
//
// Launch 1 (k_scores): per-anchor score/argmax -> 46 score-ordered buckets.
// Launch 2 (k_rg):     img preprocess blocks (independent work, overlapped)
//                      + exact rank/decode/class-list blocks.
// Launch 3 (k_pnms):   per-class IoU pairs + last-block NMS tail + reset.
// Rank = suffix(higher bins) + #greater-in-own-bucket (exact, keys unique).
// State: all mutable globals zero at load; k_pnms tail block resets them.
// ---------------------------------------------------------------------------

#define NANCH 25200
#define NCLS  80
#define KTOP  2048
#define NBIN  46
#define BCAP  4096                 // per-bucket capacity (max bin ~500 real)
#define PCAP  2048
#define CMAX  256
#define MAXDET 1000
#define CONF_T 0.4f
#define IOU_T  0.45f
#define NPIX  (640*640)
#define PREB  400                  // NPIX/(256*4) pixel blocks (4 px/thread)
#define SCB   788                  // score blocks: 8 warps x 4 anchors = 32/blk
#define RGB_  304                  // rank blocks (2432 warps, strided loop)
#define BIN_BASE 0x2FB3            // (f2u(0.4f)>>18); bins cover (0.4, 1.0]

// ------------------------- device scratch (no allocs) ----------------------
__device__ int    g_bcnt[NBIN];        // zero-init; reset by k_pnms tail
__device__ u64    g_bucket[NBIN*BCAP]; // (score_bits<<32) | ~((idx<<7)|cls)
__device__ float4 g_box[KTOP];
__device__ float  g_sc[KTOP];
__device__ float  g_cf[KTOP];
__device__ u32    g_keep[64];          // zero-init; reset by k_pnms tail
__device__ int    g_ccnt[NCLS];        // zero-init; reset by k_pnms tail
__device__ short  g_cmem [NCLS*CMAX];
__device__ float4 g_cboff[NCLS*CMAX];
__device__ float  g_carea[NCLS*CMAX];
__device__ u32    g_pairs[PCAP];
__device__ int    g_np;                // zero-init; reset by k_pnms tail
__device__ int    g_done;              // zero-init; reset by k_pnms tail

__device__ __forceinline__ u32 f2u(float f) {
    u32 b = __float_as_uint(f);
    return (b & 0x80000000u) ? ~b : (b | 0x80000000u);
}
__device__ __forceinline__ float u2f(u32 u) {
    u32 b = (u & 0x80000000u) ? (u ^ 0x80000000u) : ~u;
    return __uint_as_float(b);
}

// ---------------------------------------------------------------------------
// 1. scores only: one warp per 4 anchors, load-first, bucketed append
__global__ void __launch_bounds__(256) k_scores(const float* __restrict__ pred) {
    int bid = blockIdx.x, tid = threadIdx.x;
    int w = tid >> 5, lane = tid & 31;
    int a0 = (bid * 8 + w) * 4;
    float ob[4], f0[4], f1[4], f2[4];
#pragma unroll
    for (int k = 0; k < 4; ++k) {
        int a = a0 + k;
        int ac = (a < NANCH) ? a : (NANCH - 1);  // clamp: loads stay valid
        const float* r = pred + (long long)ac * 85;
        ob[k] = r[4];                            // broadcast (1 transaction)
        f0[k] = r[5  + lane];
        f1[k] = r[37 + lane];
        f2[k] = (lane < 16) ? r[69 + lane] : 0.0f;
    }
    u64 best[4];
#pragma unroll
    for (int k = 0; k < 4; ++k) {
        float v0 = __fmul_rn(f0[k], ob[k]);
        float v1 = __fmul_rn(f1[k], ob[k]);
        u64 c0 = ((u64)f2u(v0) << 7) | (u32)(NCLS - 1 - lane);
        u64 c1 = ((u64)f2u(v1) << 7) | (u32)(NCLS - 1 - (lane + 32));
        u64 b = (c0 > c1) ? c0 : c1;
        if (lane < 16) {
            float v2 = __fmul_rn(f2[k], ob[k]);
            u64 c2 = ((u64)f2u(v2) << 7) | (u32)(NCLS - 1 - (lane + 64));
            if (c2 > b) b = c2;
        }
        best[k] = b;
    }
#pragma unroll
    for (int o = 16; o; o >>= 1) {
#pragma unroll
        for (int k = 0; k < 4; ++k) {           // 4 independent shfl chains
            u64 oth = __shfl_xor_sync(0xffffffffu, best[k], o);
            if (oth > best[k]) best[k] = oth;
        }
    }
    if (lane == 0) {
#pragma unroll
        for (int k = 0; k < 4; ++k) {
            int a = a0 + k;
            if (a >= NANCH) continue;            // clamped duplicates masked
            float m = u2f((u32)(best[k] >> 7));
            int   c = NCLS - 1 - (int)(best[k] & 0x7F);
            if (m > CONF_T) {
                u32 sb  = f2u(m);
                int bin = (int)(sb >> 18) - BIN_BASE;
                if (bin > NBIN - 1) bin = NBIN - 1;   // m<1.0 => never fires
                if (bin < 0) bin = 0;                 // m>0.4 => never fires
                // low bits ~((a<<7)|c): decreasing in a => equal scores rank
                // lower idx first, matching top_k stability
                u32 low = ~(((u32)a << 7) | (u32)c);
                int pos = atomicAdd(&g_bcnt[bin], 1);
                if (pos < BCAP)
                    g_bucket[(u32)bin * BCAP + pos] = ((u64)sb << 32) | low;
            }
        }
    }
}

// ---------------------------------------------------------------------------
// 2. fused: image preprocess blocks (independent, overlaps with rank work)
//    | exact rank from buckets + decode + per-class member list build
__global__ void __launch_bounds__(256) k_rg(const int* __restrict__ img,
                                            const float* __restrict__ pred,
                                            float* __restrict__ out) {
    int bid = blockIdx.x, tid = threadIdx.x;
    if (bid < PREB) {
        int q = bid * 256 + tid;                 // 4-pixel group index
        const int4* i4 = (const int4*)img;
        int4 a = i4[q * 3 + 0];                  // px0.rgb px1.r
        int4 b = i4[q * 3 + 1];                  // px1.gb  px2.rg
        int4 c = i4[q * 3 + 2];                  // px2.b   px3.rgb
        const float s = 1.0f / 255.0f;
        float4 p0 = make_float4((float)a.z * s, (float)b.y * s,
                                (float)c.x  * s, (float)c.w * s); // ch2 (B)
        float4 p1 = make_float4((float)a.y * s, (float)b.x * s,
                                (float)b.w  * s, (float)c.z * s); // ch1 (G)
        float4 p2 = make_float4((float)a.x * s, (float)a.w * s,
                                (float)b.z  * s, (float)c.y * s); // ch0 (R)
        ((float4*)(out + 6000 + 0 * NPIX))[q] = p0;
        ((float4*)(out + 6000 + 1 * NPIX))[q] = p1;
        ((float4*)(out + 6000 + 2 * NPIX))[q] = p2;
        if (q < 6000) out[q] = 0.0f;             // det zero-fill
        return;
    }
    // ---- rank path ----
    __shared__ int sbc[NBIN];
    __shared__ int ssuf[NBIN + 1];
    __shared__ int hoff[NBIN];
    __shared__ int sH;
    int lane = tid & 31;
    if (tid < NBIN) { int v = g_bcnt[tid]; sbc[tid] = (v > BCAP) ? BCAP : v; }
    __syncthreads();
    if (tid == 0) {
        ssuf[NBIN] = 0;
        for (int b = NBIN - 1; b >= 0; --b) ssuf[b] = ssuf[b + 1] + sbc[b];
        int ho = 0;
        for (int b = 0; b < NBIN; ++b) {
            // bins with >=KTOP candidates strictly above them are all-out
            if (ssuf[b + 1] < KTOP) { hoff[b] = ho; ho += sbc[b]; }
            else hoff[b] = -1;
        }
        sH = ho;
    }
    __syncthreads();
    int H = sH;
    for (int h = (bid - PREB) * 8 + (tid >> 5); h < H; h += RGB_ * 8) {
        int b = 0;
        for (; b < NBIN; ++b)
            if (hoff[b] >= 0 && h >= hoff[b] && h < hoff[b] + sbc[b]) break;
        const u64* bk = &g_bucket[(u32)b * BCAP];
        u64 my = bk[h - hoff[b]];
        int n = sbc[b];
        int cgt = 0;
        for (int j = lane; j < n; j += 32)          // scan OWN bucket only
            cgt += (__ldg(&bk[j]) > my) ? 1 : 0;
#pragma unroll
        for (int o = 16; o; o >>= 1)
            cgt += __shfl_xor_sync(0xffffffffu, cgt, o);
        int r = ssuf[b + 1] + cgt;                   // exact unique rank
        if (r >= KTOP || lane != 0) continue;
        u32 v   = ~(u32)my;
        int idx = (int)(v >> 7);
        int cls = (int)(v & 127u);
        float sc = u2f((u32)(my >> 32));
        const float* p = pred + (long long)idx * 85;
        float x = p[0], y = p[1], w = p[2], h2 = p[3];
        float hw = __fmul_rn(w, 0.5f), hh = __fmul_rn(h2, 0.5f);
        float x1 = __fsub_rn(x, hw), y1 = __fsub_rn(y, hh);
        float x2 = __fadd_rn(x, hw), y2 = __fadd_rn(y, hh);
        float cf  = (float)cls;
        float off = __fmul_rn(cf, 7680.0f);
        float ox1 = __fadd_rn(x1, off), oy1 = __fadd_rn(y1, off);
        float ox2 = __fadd_rn(x2, off), oy2 = __fadd_rn(y2, off);
        g_box[r] = make_float4(x1, y1, x2, y2);
        g_sc[r]  = sc;
        g_cf[r]  = cf;
        atomicOr(&g_keep[r >> 5], 1u << (r & 31));   // all appended > CONF_T
        int pos = atomicAdd(&g_ccnt[cls], 1);
        if (pos < CMAX) {
            int e = cls * CMAX + pos;
            g_cmem[e]  = (short)r;
            g_cboff[e] = make_float4(ox1, oy1, ox2, oy2);
            g_carea[e] = __fmul_rn(__fsub_rn(ox2, ox1), __fsub_rn(oy2, oy1));
        }
    }
}

// ---------------------------------------------------------------------------
// 3. fused pairs + NMS: one block per class (speculative member loads);
//    LAST block runs sort + greedy chain + writeback + state reset.
//    Release/acquire: per-thread __threadfence() before the barrier that
//    precedes the g_done increment; tail fences before reading pairs.
//    Cross-class IoU provably == 0 (class offset 7680 > max box extent).
__global__ void __launch_bounds__(128) k_pnms(float* __restrict__ out) {
    __shared__ float4 sbx[128];
    __shared__ float  sar[128];
    __shared__ short  srow[128];
    __shared__ int    sm;
    __shared__ int    isLast;
    int c = blockIdx.x, tid = threadIdx.x;
    int e = c * CMAX + tid;
    // speculative loads (slots >= m unused garbage; class counts ~26 << 128)
    sbx[tid]  = g_cboff[e];
    sar[tid]  = g_carea[e];
    srow[tid] = g_cmem[e];
    if (tid == 0) sm = g_ccnt[c];
    __syncthreads();
    int m = sm; if (m > 128) m = 128;
    if (m >= 2) {
        for (int t = tid; t < m * m; t += 128) {
            int a = t / m, b = t - a * m;
            if (a >= b) continue;
            float4 A = sbx[a], B = sbx[b];
            float ltx = fmaxf(A.x, B.x), lty = fmaxf(A.y, B.y);
            float rbx = fminf(A.z, B.z), rby = fminf(A.w, B.w);
            float wx = fmaxf(__fsub_rn(rbx, ltx), 0.0f);
            float wy = fmaxf(__fsub_rn(rby, lty), 0.0f);
            float inter = __fmul_rn(wx, wy);
            if (inter <= 0.0f) continue;        // iou = 0 exactly
            float den = __fadd_rn(__fsub_rn(__fadd_rn(sar[a], sar[b]), inter), 1e-7f);
            if (__fdiv_rn(inter, den) > IOU_T) {
                int i = srow[a], j = srow[b];
                if (i > j) { int s = i; i = j; j = s; }
                int p = atomicAdd(&g_np, 1);
                if (p < PCAP) atomicExch(&g_pairs[p], ((u32)i << 11) | (u32)j);
            }
        }
    }
    // ---- release: every thread fences its writes, then g_done increment ----
    __threadfence();
    __syncthreads();
    if (tid == 0) {
        int v = atomicAdd(&g_done, 1);
        isLast = (v == NCLS - 1);
    }
    __syncthreads();
    if (!isLast) return;
    __threadfence();                            // acquire before reading pairs

    __shared__ u32 sp[PCAP];
    __shared__ u32 keep[64];
    __shared__ int wpre[64];
    int np = g_np; if (np > PCAP) np = PCAP;
    if (tid < 64) keep[tid] = g_keep[tid];
    for (int i = tid; i < np; i += 128) sp[i] = g_pairs[i];
    __syncthreads();
    if (np > 1) {
        int npad = 2; while (npad < np) npad <<= 1;
        for (int i = tid; i < npad; i += 128)
            if (i >= np) sp[i] = 0xFFFFFFFFu;
        __syncthreads();
        for (int k = 2; k <= npad; k <<= 1) {
            for (int j = k >> 1; j; j >>= 1) {
                for (int i = tid; i < npad; i += 128) {
                    int x = i ^ j;
                    if (x > i) {
                        u32 a = sp[i], b = sp[x];
                        bool up = ((i & k) == 0);
                        if (up ? (a > b) : (a < b)) { sp[i] = b; sp[x] = a; }
                    }
                }
                __syncthreads();
            }
        }
    }
    if (tid == 0) {   // greedy chain: ascending suppressor rank == reference
        for (int p = 0; p < np; ++p) {
            u32 v = sp[p];
            int i = (int)(v >> 11), j = (int)(v & 2047u);
            if ((keep[i >> 5] >> (i & 31)) & 1u)
                keep[j >> 5] &= ~(1u << (j & 31));
        }
        int s = 0;
        for (int w = 0; w < 64; ++w) { wpre[w] = s; s += __popc(keep[w]); }
    }
    __syncthreads();
    for (int r = tid; r < KTOP; r += 128) {
        u32 kw = keep[r >> 5];
        if ((kw >> (r & 31)) & 1u) {
            int pos = wpre[r >> 5] + __popc(kw & ((1u << (r & 31)) - 1u));
            if (pos < MAXDET) {
                float4 b = g_box[r];
                out[pos * 6 + 0] = b.x;
                out[pos * 6 + 1] = b.y;
                out[pos * 6 + 2] = b.z;
                out[pos * 6 + 3] = b.w;
                out[pos * 6 + 4] = g_sc[r];
                out[pos * 6 + 5] = g_cf[r];
            }
        }
    }
    // ---- state reset for the next invocation (sole live block) ----
    if (tid < NBIN) g_bcnt[tid] = 0;
    if (tid < NCLS) g_ccnt[tid] = 0;
    if (tid < 64)   g_keep[tid] = 0u;
    if (tid == 0) { g_np = 0; g_done = 0; }
}

// ------------------------------ launch --------------------------------------
extern "C" void kernel_launch(void* const* d_in, const int* in_sizes, int n_in,
                              void* d_out, int out_size) {
    const int*   img  = (const int*)d_in[0];
    const float* pred = (const float*)d_in[1];
    float*       out  = (float*)d_out;

    k_scores <<< SCB, 256 >>> (pred);
    k_rg     <<< PREB + RGB_, 256 >>> (img, pred, out);
    k_pnms   <<< NCLS, 128 >>> (out);
}

// round 17
// speedup vs baseline: 1.0073x; 1.0073x over previous
#include <cuda_runtime.h>
#include <cstdint>

typedef unsigned long long u64;
typedef unsigned int u32;

// ---------------------------------------------------------------------------
// GhInfer_19104014533112 : YOLO NMS post-process on GB300 — 3-launch pipeline
// out[0:6000) det (1000x6) fp32 ; out[6000:1234800) x (1,3,640,640) fp32
// in[0] img int32 (640*640*3) ; in[1] pred fp32 (8*25200*85), batch 0 only
//
// Launch 1 (k_scores): ONE ANCHOR PER WARP (occupancy >> stall coverage),
//                      score/argmax -> 46 score-ordered buckets.
// Launch 2 (k_rg):     img preprocess blocks + exact rank/decode/class lists.
// Launch 3 (k_pnms):   per-class IoU pairs + last-block NMS tail + reset.
// Rank = suffix(higher bins) + #greater-in-own-bucket (exact, keys unique).
// State: all mutable globals zero at load; k_pnms tail block resets them.
// ---------------------------------------------------------------------------

#define NANCH 25200
#define NCLS  80
#define KTOP  2048
#define NBIN  46
#define BCAP  4096                 // per-bucket capacity (max bin ~500 real)
#define PCAP  2048
#define CMAX  256
#define MAXDET 1000
#define CONF_T 0.4f
#define IOU_T  0.45f
#define NPIX  (640*640)
#define PREB  400                  // NPIX/(256*4) pixel blocks (4 px/thread)
#define SCB   3150                 // score blocks: 8 warps x 1 anchor = 8/blk
#define RGB_  304                  // rank blocks (2432 warps, strided loop)
#define BIN_BASE 0x2FB3            // (f2u(0.4f)>>18); bins cover (0.4, 1.0]

// ------------------------- device scratch (no allocs) ----------------------
__device__ int    g_bcnt[NBIN];        // zero-init; reset by k_pnms tail
__device__ u64    g_bucket[NBIN*BCAP]; // (score_bits<<32) | ~((idx<<7)|cls)
__device__ float4 g_box[KTOP];
__device__ float  g_sc[KTOP];
__device__ float  g_cf[KTOP];
__device__ u32    g_keep[64];          // zero-init; reset by k_pnms tail
__device__ int    g_ccnt[NCLS];        // zero-init; reset by k_pnms tail
__device__ short  g_cmem [NCLS*CMAX];
__device__ float4 g_cboff[NCLS*CMAX];
__device__ float  g_carea[NCLS*CMAX];
__device__ u32    g_pairs[PCAP];
__device__ int    g_np;                // zero-init; reset by k_pnms tail
__device__ int    g_done;              // zero-init; reset by k_pnms tail

__device__ __forceinline__ u32 f2u(float f) {
    u32 b = __float_as_uint(f);
    return (b & 0x80000000u) ? ~b : (b | 0x80000000u);
}
__device__ __forceinline__ float u2f(u32 u) {
    u32 b = (u & 0x80000000u) ? (u ^ 0x80000000u) : ~u;
    return __uint_as_float(b);
}

// ---------------------------------------------------------------------------
// 1. scores: ONE anchor per warp (max occupancy / stall coverage)
__global__ void __launch_bounds__(256) k_scores(const float* __restrict__ pred) {
    int tid = threadIdx.x;
    int w = tid >> 5, lane = tid & 31;
    int a = blockIdx.x * 8 + w;
    int ac = (a < NANCH) ? a : (NANCH - 1);      // clamp: loads stay valid
    const float* r = pred + (long long)ac * 85;
    float ob = r[4];                             // broadcast (1 transaction)
    float f0 = r[5  + lane];
    float f1 = r[37 + lane];
    float f2 = (lane < 16) ? r[69 + lane] : 0.0f;

    float v0 = __fmul_rn(f0, ob);
    float v1 = __fmul_rn(f1, ob);
    u64 c0 = ((u64)f2u(v0) << 7) | (u32)(NCLS - 1 - lane);
    u64 c1 = ((u64)f2u(v1) << 7) | (u32)(NCLS - 1 - (lane + 32));
    u64 best = (c0 > c1) ? c0 : c1;
    if (lane < 16) {
        float v2 = __fmul_rn(f2, ob);
        u64 c2 = ((u64)f2u(v2) << 7) | (u32)(NCLS - 1 - (lane + 64));
        if (c2 > best) best = c2;
    }
#pragma unroll
    for (int o = 16; o; o >>= 1) {
        u64 oth = __shfl_xor_sync(0xffffffffu, best, o);
        if (oth > best) best = oth;
    }
    if (lane == 0 && a < NANCH) {
        float m = u2f((u32)(best >> 7));
        int   c = NCLS - 1 - (int)(best & 0x7F);
        if (m > CONF_T) {
            u32 sb  = f2u(m);
            int bin = (int)(sb >> 18) - BIN_BASE;
            if (bin > NBIN - 1) bin = NBIN - 1;  // m<1.0 => never fires
            if (bin < 0) bin = 0;                // m>0.4 => never fires
            // low bits ~((a<<7)|c): decreasing in a => equal scores rank
            // lower idx first, matching top_k stability
            u32 low = ~(((u32)a << 7) | (u32)c);
            int pos = atomicAdd(&g_bcnt[bin], 1);
            if (pos < BCAP)
                g_bucket[(u32)bin * BCAP + pos] = ((u64)sb << 32) | low;
        }
    }
}

// ---------------------------------------------------------------------------
// 2. fused: image preprocess blocks (independent, overlaps with rank work)
//    | exact rank from buckets + decode + per-class member list build
__global__ void __launch_bounds__(256) k_rg(const int* __restrict__ img,
                                            const float* __restrict__ pred,
                                            float* __restrict__ out) {
    int bid = blockIdx.x, tid = threadIdx.x;
    if (bid < PREB) {
        int q = bid * 256 + tid;                 // 4-pixel group index
        const int4* i4 = (const int4*)img;
        int4 a = i4[q * 3 + 0];                  // px0.rgb px1.r
        int4 b = i4[q * 3 + 1];                  // px1.gb  px2.rg
        int4 c = i4[q * 3 + 2];                  // px2.b   px3.rgb
        const float s = 1.0f / 255.0f;
        float4 p0 = make_float4((float)a.z * s, (float)b.y * s,
                                (float)c.x  * s, (float)c.w * s); // ch2 (B)
        float4 p1 = make_float4((float)a.y * s, (float)b.x * s,
                                (float)b.w  * s, (float)c.z * s); // ch1 (G)
        float4 p2 = make_float4((float)a.x * s, (float)a.w * s,
                                (float)b.z  * s, (float)c.y * s); // ch0 (R)
        ((float4*)(out + 6000 + 0 * NPIX))[q] = p0;
        ((float4*)(out + 6000 + 1 * NPIX))[q] = p1;
        ((float4*)(out + 6000 + 2 * NPIX))[q] = p2;
        if (q < 6000) out[q] = 0.0f;             // det zero-fill
        return;
    }
    // ---- rank path ----
    __shared__ int sbc[NBIN];
    __shared__ int ssuf[NBIN + 1];
    __shared__ int hoff[NBIN];
    __shared__ int sH;
    int lane = tid & 31;
    if (tid < NBIN) { int v = g_bcnt[tid]; sbc[tid] = (v > BCAP) ? BCAP : v; }
    __syncthreads();
    if (tid == 0) {
        ssuf[NBIN] = 0;
        for (int b = NBIN - 1; b >= 0; --b) ssuf[b] = ssuf[b + 1] + sbc[b];
        int ho = 0;
        for (int b = 0; b < NBIN; ++b) {
            // bins with >=KTOP candidates strictly above them are all-out
            if (ssuf[b + 1] < KTOP) { hoff[b] = ho; ho += sbc[b]; }
            else hoff[b] = -1;
        }
        sH = ho;
    }
    __syncthreads();
    int H = sH;
    for (int h = (bid - PREB) * 8 + (tid >> 5); h < H; h += RGB_ * 8) {
        int b = 0;
        for (; b < NBIN; ++b)
            if (hoff[b] >= 0 && h >= hoff[b] && h < hoff[b] + sbc[b]) break;
        const u64* bk = &g_bucket[(u32)b * BCAP];
        u64 my = bk[h - hoff[b]];
        int n = sbc[b];
        int cgt = 0;
        for (int j = lane; j < n; j += 32)          // scan OWN bucket only
            cgt += (__ldg(&bk[j]) > my) ? 1 : 0;
#pragma unroll
        for (int o = 16; o; o >>= 1)
            cgt += __shfl_xor_sync(0xffffffffu, cgt, o);
        int r = ssuf[b + 1] + cgt;                   // exact unique rank
        if (r >= KTOP || lane != 0) continue;
        u32 v   = ~(u32)my;
        int idx = (int)(v >> 7);
        int cls = (int)(v & 127u);
        float sc = u2f((u32)(my >> 32));
        const float* p = pred + (long long)idx * 85;
        float x = p[0], y = p[1], w = p[2], h2 = p[3];
        float hw = __fmul_rn(w, 0.5f), hh = __fmul_rn(h2, 0.5f);
        float x1 = __fsub_rn(x, hw), y1 = __fsub_rn(y, hh);
        float x2 = __fadd_rn(x, hw), y2 = __fadd_rn(y, hh);
        float cf  = (float)cls;
        float off = __fmul_rn(cf, 7680.0f);
        float ox1 = __fadd_rn(x1, off), oy1 = __fadd_rn(y1, off);
        float ox2 = __fadd_rn(x2, off), oy2 = __fadd_rn(y2, off);
        g_box[r] = make_float4(x1, y1, x2, y2);
        g_sc[r]  = sc;
        g_cf[r]  = cf;
        atomicOr(&g_keep[r >> 5], 1u << (r & 31));   // all appended > CONF_T
        int pos = atomicAdd(&g_ccnt[cls], 1);
        if (pos < CMAX) {
            int e = cls * CMAX + pos;
            g_cmem[e]  = (short)r;
            g_cboff[e] = make_float4(ox1, oy1, ox2, oy2);
            g_carea[e] = __fmul_rn(__fsub_rn(ox2, ox1), __fsub_rn(oy2, oy1));
        }
    }
}

// ---------------------------------------------------------------------------
// 3. fused pairs + NMS: one block per class (speculative member loads);
//    LAST block runs sort + greedy chain + writeback + state reset.
//    Release/acquire: per-thread __threadfence() before the barrier that
//    precedes the g_done increment; tail fences before reading pairs.
//    Cross-class IoU provably == 0 (class offset 7680 > max box extent).
__global__ void __launch_bounds__(128) k_pnms(float* __restrict__ out) {
    __shared__ float4 sbx[128];
    __shared__ float  sar[128];
    __shared__ short  srow[128];
    __shared__ int    sm;
    __shared__ int    isLast;
    int c = blockIdx.x, tid = threadIdx.x;
    int e = c * CMAX + tid;
    // speculative loads (slots >= m unused garbage; class counts ~26 << 128)
    sbx[tid]  = g_cboff[e];
    sar[tid]  = g_carea[e];
    srow[tid] = g_cmem[e];
    if (tid == 0) sm = g_ccnt[c];
    __syncthreads();
    int m = sm; if (m > 128) m = 128;
    if (m >= 2) {
        for (int t = tid; t < m * m; t += 128) {
            int a = t / m, b = t - a * m;
            if (a >= b) continue;
            float4 A = sbx[a], B = sbx[b];
            float ltx = fmaxf(A.x, B.x), lty = fmaxf(A.y, B.y);
            float rbx = fminf(A.z, B.z), rby = fminf(A.w, B.w);
            float wx = fmaxf(__fsub_rn(rbx, ltx), 0.0f);
            float wy = fmaxf(__fsub_rn(rby, lty), 0.0f);
            float inter = __fmul_rn(wx, wy);
            if (inter <= 0.0f) continue;        // iou = 0 exactly
            float den = __fadd_rn(__fsub_rn(__fadd_rn(sar[a], sar[b]), inter), 1e-7f);
            if (__fdiv_rn(inter, den) > IOU_T) {
                int i = srow[a], j = srow[b];
                if (i > j) { int s = i; i = j; j = s; }
                int p = atomicAdd(&g_np, 1);
                if (p < PCAP) atomicExch(&g_pairs[p], ((u32)i << 11) | (u32)j);
            }
        }
    }
    // ---- release: every thread fences its writes, then g_done increment ----
    __threadfence();
    __syncthreads();
    if (tid == 0) {
        int v = atomicAdd(&g_done, 1);
        isLast = (v == NCLS - 1);
    }
    __syncthreads();
    if (!isLast) return;
    __threadfence();                            // acquire before reading pairs

    __shared__ u32 sp[PCAP];
    __shared__ u32 keep[64];
    __shared__ int wpre[64];
    int np = g_np; if (np > PCAP) np = PCAP;
    if (tid < 64) keep[tid] = g_keep[tid];
    for (int i = tid; i < np; i += 128) sp[i] = g_pairs[i];
    __syncthreads();
    if (np > 1) {
        int npad = 2; while (npad < np) npad <<= 1;
        for (int i = tid; i < npad; i += 128)
            if (i >= np) sp[i] = 0xFFFFFFFFu;
        __syncthreads();
        for (int k = 2; k <= npad; k <<= 1) {
            for (int j = k >> 1; j; j >>= 1) {
                for (int i = tid; i < npad; i += 128) {
                    int x = i ^ j;
                    if (x > i) {
                        u32 a = sp[i], b = sp[x];
                        bool up = ((i & k) == 0);
                        if (up ? (a > b) : (a < b)) { sp[i] = b; sp[x] = a; }
                    }
                }
                __syncthreads();
            }
        }
    }
    if (tid == 0) {   // greedy chain: ascending suppressor rank == reference
        for (int p = 0; p < np; ++p) {
            u32 v = sp[p];
            int i = (int)(v >> 11), j = (int)(v & 2047u);
            if ((keep[i >> 5] >> (i & 31)) & 1u)
                keep[j >> 5] &= ~(1u << (j & 31));
        }
        int s = 0;
        for (int w = 0; w < 64; ++w) { wpre[w] = s; s += __popc(keep[w]); }
    }
    __syncthreads();
    for (int r = tid; r < KTOP; r += 128) {
        u32 kw = keep[r >> 5];
        if ((kw >> (r & 31)) & 1u) {
            int pos = wpre[r >> 5] + __popc(kw & ((1u << (r & 31)) - 1u));
            if (pos < MAXDET) {
                float4 b = g_box[r];
                out[pos * 6 + 0] = b.x;
                out[pos * 6 + 1] = b.y;
                out[pos * 6 + 2] = b.z;
                out[pos * 6 + 3] = b.w;
                out[pos * 6 + 4] = g_sc[r];
                out[pos * 6 + 5] = g_cf[r];
            }
        }
    }
    // ---- state reset for the next invocation (sole live block) ----
    if (tid < NBIN) g_bcnt[tid] = 0;
    if (tid < NCLS) g_ccnt[tid] = 0;
    if (tid < 64)   g_keep[tid] = 0u;
    if (tid == 0) { g_np = 0; g_done = 0; }
}

// ------------------------------ launch --------------------------------------
extern "C" void kernel_launch(void* const* d_in, const int* in_sizes, int n_in,
                              void* d_out, int out_size) {
    const int*   img  = (const int*)d_in[0];
    const float* pred = (const float*)d_in[1];
    float*       out  = (float*)d_out;

    k_scores <<< SCB, 256 >>> (pred);
    k_rg     <<< PREB + RGB_, 256 >>> (img, pred, out);
    k_pnms   <<< NCLS, 128 >>> (out);
}